// round 13
// baseline (speedup 1.0000x reference)
#include <cuda_runtime.h>
#include <cstdint>

#define B_    32
#define C_    320
#define H_    64
#define W_    64
#define CTXD  1024
#define KIN   1026     // 1024 context channels + 2 indicator channels
#define KPAD  1056     // padded to 32-multiple for the transpose tiling
#define CHW   16
#define P_    256      // 16*16 spatial positions
#define PROWS 18       // padded rows
#define PCOLS 18       // padded cols, in f32x2 units (stride chosen for conflict-free LDS)
#define PP    (PROWS * PCOLS)   // 324 f32x2 cells per padded channel map
#define CICH  12       // input-channel chunk staged in SMEM

typedef unsigned long long ull;

// ---- scratch (device globals: allocation-free, zero-initialized) ----
__device__ float g_ctxT[(size_t)B_ * KPAD * P_];                 // transposed ctx (B, ci, p)
__device__ __align__(16) ull g_cx1d[((size_t)B_ * C_ + 4) * PP]; // conv1+SiLU, duplicated (v,v) pairs, padded 18x18 (+4 ch zero pad)
__device__ float g_cx2 [(size_t)B_ * C_ * P_];                   // conv2 out
__device__ int   g_bbi [B_ * 8];                                 // x1,y1,x2,y2,ok,dx,dy

// ---- packed fp32x2 helpers (FFMA2: 2x fp32 FMA per issue, exact fp32) ----
__device__ __forceinline__ ull ffma2(ull a, ull b, ull c) {
    ull d;
    asm("fma.rn.f32x2 %0, %1, %2, %3;" : "=l"(d) : "l"(a), "l"(b), "l"(c));
    return d;
}
__device__ __forceinline__ ull dup2(float x) {
    ull d;
    asm("mov.b64 %0, {%1, %1};" : "=l"(d) : "f"(x), "f"(x));
    return d;
}
__device__ __forceinline__ float lo32(ull a) { return __uint_as_float((unsigned)(a & 0xffffffffull)); }
__device__ __forceinline__ float hi32(ull a) { return __uint_as_float((unsigned)(a >> 32)); }

// ---------------------------------------------------------------------------
// bbox -> int precompute (matches jnp: (bbox*64) truncated to int32)
// ---------------------------------------------------------------------------
__global__ void bbox_prep_kernel(const float* __restrict__ bbox) {
    int b = threadIdx.x;
    if (b >= B_) return;
    int x1 = (int)(bbox[4 * b + 0] * 64.0f);
    int y1 = (int)(bbox[4 * b + 1] * 64.0f);
    int x2 = (int)(bbox[4 * b + 2] * 64.0f);
    int y2 = (int)(bbox[4 * b + 3] * 64.0f);
    x2 = max(x2, x1 + 1);
    y2 = max(y2, y1 + 1);
    int ok = (y2 <= H_) && (x2 <= W_) && (y1 >= 0) && (x1 >= 0);
    int* o = &g_bbi[b * 8];
    o[0] = x1; o[1] = y1; o[2] = x2; o[3] = y2;
    o[4] = ok; o[5] = x2 - x1; o[6] = y2 - y1;
}

// ---------------------------------------------------------------------------
// context (B,256,1024) + indicator -> g_ctxT (B, 1056, 256)
// ---------------------------------------------------------------------------
__global__ void transpose_kernel(const float* __restrict__ context,
                                 const float* __restrict__ indicator) {
    __shared__ float tile[32][33];
    int b   = blockIdx.z;
    int ci0 = blockIdx.y * 32;
    int p0  = blockIdx.x * 32;
    int tx = threadIdx.x, ty = threadIdx.y;
#pragma unroll
    for (int j = 0; j < 4; ++j) {
        int p  = p0 + ty + 8 * j;
        int ci = ci0 + tx;
        float v;
        if (ci < CTXD)      v = context[((size_t)b * P_ + p) * CTXD + ci];
        else if (ci < KIN)  v = indicator[b * 2 + (ci - CTXD)];
        else                v = 0.0f;
        tile[ty + 8 * j][tx] = v;
    }
    __syncthreads();
#pragma unroll
    for (int j = 0; j < 4; ++j) {
        int ci = ci0 + ty + 8 * j;
        int p  = p0 + tx;
        g_ctxT[((size_t)b * KPAD + ci) * P_ + p] = tile[tx][ty + 8 * j];
    }
}

// ---------------------------------------------------------------------------
// Inner-product core. Thread tile = 4x x 2y x 4co; CTA tile = 32co x 256pos.
// Per ci: 18 LDS.64 weight preload + 24 LDS.64 x (pre-duplicated, conflict-
// free banks) feeding 144 FFMA2. No MOVs in the loop body.
// x layout: sX[ci][row*18 + col] holds (v,v); interior col = px+1, row = py+1.
// Thread map: co_h = t&7, pg = t>>3, y2 = pg&7 (out rows 2y2,2y2+1),
//             x0 = (pg>>3)*4. Warp = 4 consecutive y2 at one x0
//             -> x addresses hit banks {0,8,16,24} (72 floats apart).
// ---------------------------------------------------------------------------
#define CONV_CORE2(sX, sW, acc, y2, x0, co_h)                                      \
    _Pragma("unroll 1")                                                            \
    for (int ci = 0; ci < CICH; ++ci) {                                            \
        ull wreg[9][2];                                                            \
        _Pragma("unroll")                                                          \
        for (int tap = 0; tap < 9; ++tap) {                                        \
            const ull* wp = reinterpret_cast<const ull*>(&sW[ci][tap][(co_h) * 4]);\
            wreg[tap][0] = wp[0];                                                  \
            wreg[tap][1] = wp[1];                                                  \
        }                                                                          \
        _Pragma("unroll")                                                          \
        for (int r = 0; r < 4; ++r) {                                              \
            int rb = (2 * (y2) + r) * PCOLS + (x0);                                \
            ull xd[6];                                                             \
            _Pragma("unroll")                                                      \
            for (int i = 0; i < 6; ++i) xd[i] = sX[ci][rb + i];                    \
            if (r <= 2) {                                                          \
                _Pragma("unroll")                                                  \
                for (int dx = 0; dx < 3; ++dx)                                     \
                    _Pragma("unroll")                                              \
                    for (int j = 0; j < 4; ++j) {                                  \
                        acc[0][j][0] = ffma2(wreg[r*3+dx][0], xd[dx+j], acc[0][j][0]); \
                        acc[0][j][1] = ffma2(wreg[r*3+dx][1], xd[dx+j], acc[0][j][1]); \
                    }                                                              \
            }                                                                      \
            if (r >= 1) {                                                          \
                _Pragma("unroll")                                                  \
                for (int dx = 0; dx < 3; ++dx)                                     \
                    _Pragma("unroll")                                              \
                    for (int j = 0; j < 4; ++j) {                                  \
                        acc[1][j][0] = ffma2(wreg[(r-1)*3+dx][0], xd[dx+j], acc[1][j][0]); \
                        acc[1][j][1] = ffma2(wreg[(r-1)*3+dx][1], xd[dx+j], acc[1][j][1]); \
                    }                                                              \
            }                                                                      \
        }                                                                          \
    }

// ---------------------------------------------------------------------------
// conv1 (K=1026 via 86 chunks of 12) + SiLU -> g_cx1d (duplicated, padded)
// ---------------------------------------------------------------------------
__global__ __launch_bounds__(256, 2) void conv1_kernel(const float* __restrict__ w_in,
                                                       const float* __restrict__ b_in) {
    __shared__ __align__(16) ull sX[CICH][PP];
    __shared__ __align__(8)  float sW[CICH][9][32];
    int t   = threadIdx.x;
    int co0 = blockIdx.x * 32;
    int b   = blockIdx.y;

    // zero the padded borders once; interior is rewritten every chunk
    for (int idx = t; idx < CICH * PP; idx += 256) {
        int q  = idx % PP;
        int qy = q / PCOLS, qx = q % PCOLS;
        if (qy == 0 || qy == 17 || qx == 0 || qx == 17) (&sX[0][0])[idx] = 0ull;
    }

    int co_h = t & 7;
    int pg   = t >> 3;
    int y2   = pg & 7;
    int x0   = (pg >> 3) * 4;

    ull acc[2][4][2];
#pragma unroll
    for (int o = 0; o < 2; ++o)
#pragma unroll
        for (int j = 0; j < 4; ++j) { acc[o][j][0] = 0ull; acc[o][j][1] = 0ull; }

    const int NCH = (KIN + CICH - 1) / CICH;   // 86
    for (int ch = 0; ch < NCH; ++ch) {
        int ci0 = ch * CICH;
        __syncthreads();
        // stage X interior, duplicated (coalesced reads from transposed layout)
        for (int idx = t; idx < CICH * P_; idx += 256) {
            int ci = idx >> 8;
            int p  = idx & 255;
            int py = p >> 4, px = p & 15;
            float v = g_ctxT[((size_t)b * KPAD + ci0 + ci) * P_ + p];
            sX[ci][(py + 1) * PCOLS + px + 1] = dup2(v);
        }
        // stage W (zero past K=1026)
        for (int idx = t; idx < CICH * 9 * 32; idx += 256) {
            int co = idx & 31;
            int k  = idx >> 5;
            int ci = k / 9, tap = k - ci * 9;
            int gci = ci0 + ci;
            sW[ci][tap][co] = (gci < KIN)
                ? w_in[((size_t)(co0 + co) * KIN + gci) * 9 + tap] : 0.0f;
        }
        __syncthreads();
        CONV_CORE2(sX, sW, acc, y2, x0, co_h)
    }

    // epilogue: bias + SiLU, duplicated stores into padded interior
#pragma unroll
    for (int cp = 0; cp < 2; ++cp) {
        int co = co0 + co_h * 4 + cp * 2;
        float bl = b_in[co], bh = b_in[co + 1];
#pragma unroll
        for (int o = 0; o < 2; ++o) {
            int yy = 2 * y2 + o;
            size_t base0 = ((size_t)(b * C_ + co))     * PP + (yy + 1) * PCOLS + x0 + 1;
            size_t base1 = ((size_t)(b * C_ + co + 1)) * PP + (yy + 1) * PCOLS + x0 + 1;
#pragma unroll
            for (int j = 0; j < 4; ++j) {
                float a = lo32(acc[o][j][cp]) + bl;
                float c = hi32(acc[o][j][cp]) + bh;
                float s0 = a / (1.0f + expf(-a));
                float s1 = c / (1.0f + expf(-c));
                g_cx1d[base0 + j] = dup2(s0);
                g_cx1d[base1 + j] = dup2(s1);
            }
        }
    }
}

// ---------------------------------------------------------------------------
// conv2 (K=320 via 27 chunks of 12) -> g_cx2
// g_cx1d already duplicated + zero-padded -> staging is a flat float4 copy
// ---------------------------------------------------------------------------
__global__ __launch_bounds__(256, 2) void conv2_kernel(const float* __restrict__ w_out,
                                                       const float* __restrict__ b_out) {
    __shared__ __align__(16) ull sX[CICH][PP];
    __shared__ __align__(8)  float sW[CICH][9][32];
    int t   = threadIdx.x;
    int co0 = blockIdx.x * 32;
    int b   = blockIdx.y;

    int co_h = t & 7;
    int pg   = t >> 3;
    int y2   = pg & 7;
    int x0   = (pg >> 3) * 4;

    ull acc[2][4][2];
#pragma unroll
    for (int o = 0; o < 2; ++o)
#pragma unroll
        for (int j = 0; j < 4; ++j) { acc[o][j][0] = 0ull; acc[o][j][1] = 0ull; }

    const int NCH = (C_ + CICH - 1) / CICH;    // 27
    for (int ch = 0; ch < NCH; ++ch) {
        int ci0 = ch * CICH;
        __syncthreads();
        {   // flat copy incl. borders (channels past C_ are zero pad)
            const float4* src = reinterpret_cast<const float4*>(
                g_cx1d + (size_t)(b * C_ + ci0) * PP);
            float4* dst = reinterpret_cast<float4*>(&sX[0][0]);
            for (int idx = t; idx < CICH * PP / 2; idx += 256) dst[idx] = src[idx];
        }
        for (int idx = t; idx < CICH * 9 * 32; idx += 256) {
            int co = idx & 31;
            int k  = idx >> 5;
            int ci = k / 9, tap = k - ci * 9;
            int gci = ci0 + ci;
            sW[ci][tap][co] = (gci < C_)
                ? w_out[((size_t)(co0 + co) * C_ + gci) * 9 + tap] : 0.0f;
        }
        __syncthreads();
        CONV_CORE2(sX, sW, acc, y2, x0, co_h)
    }

    // epilogue: bias; per-(row,co) float4 stores (x0 16B-aligned in 16-wide rows)
#pragma unroll
    for (int cp = 0; cp < 2; ++cp) {
        int co = co0 + co_h * 4 + cp * 2;
        float bl = b_out[co], bh = b_out[co + 1];
#pragma unroll
        for (int o = 0; o < 2; ++o) {
            int yy = 2 * y2 + o;
            float4 vl, vh;
            vl.x = lo32(acc[o][0][cp]) + bl; vl.y = lo32(acc[o][1][cp]) + bl;
            vl.z = lo32(acc[o][2][cp]) + bl; vl.w = lo32(acc[o][3][cp]) + bl;
            vh.x = hi32(acc[o][0][cp]) + bh; vh.y = hi32(acc[o][1][cp]) + bh;
            vh.z = hi32(acc[o][2][cp]) + bh; vh.w = hi32(acc[o][3][cp]) + bh;
            size_t base = ((size_t)(b * C_ + co)) * P_ + yy * CHW + x0;
            *reinterpret_cast<float4*>(&g_cx2[base])      = vl;
            *reinterpret_cast<float4*>(&g_cx2[base + P_]) = vh;
        }
    }
}

// ---------------------------------------------------------------------------
// out = global_x + masked nearest-neighbor upsample of g_cx2 into the bbox
// ---------------------------------------------------------------------------
__global__ __launch_bounds__(256) void fuse_kernel(const float* __restrict__ gx,
                                                   float* __restrict__ out) {
    int idx = blockIdx.x * 256 + threadIdx.x;    // (bc*64 + y)*16 + xg
    int xg = idx & 15;
    int y  = (idx >> 4) & 63;
    int bc = idx >> 10;                           // b*C_ + c
    int b  = bc / C_;

    size_t gbase = (((size_t)bc * 64 + y) * 64) + xg * 4;
    float4 g = *reinterpret_cast<const float4*>(gx + gbase);

    const int* bb = &g_bbi[b * 8];
    int x1 = bb[0], y1 = bb[1], x2 = bb[2], y2 = bb[3];
    int ok = bb[4], dxs = bb[5], dys = bb[6];

    if (ok && y >= y1 && y < y2) {
        int sy = (y - y1) * CHW / dys;
        sy = min(max(sy, 0), CHW - 1);
        const float* lrow = g_cx2 + (size_t)bc * P_ + sy * CHW;
        int xb = xg * 4;
        float* gv = reinterpret_cast<float*>(&g);
#pragma unroll
        for (int k = 0; k < 4; ++k) {
            int xx = xb + k;
            if (xx >= x1 && xx < x2) {
                int sx = (xx - x1) * CHW / dxs;
                sx = min(max(sx, 0), CHW - 1);
                gv[k] += lrow[sx];
            }
        }
    }
    *reinterpret_cast<float4*>(out + gbase) = g;
}

// ---------------------------------------------------------------------------
extern "C" void kernel_launch(void* const* d_in, const int* in_sizes, int n_in,
                              void* d_out, int out_size) {
    const float* global_x  = (const float*)d_in[0];
    const float* context   = (const float*)d_in[1];
    const float* indicator = (const float*)d_in[2];
    const float* bbox      = (const float*)d_in[3];
    const float* w_in      = (const float*)d_in[4];
    const float* b_in      = (const float*)d_in[5];
    const float* w_out     = (const float*)d_in[6];
    const float* b_out     = (const float*)d_in[7];
    float* out = (float*)d_out;

    bbox_prep_kernel<<<1, 32>>>(bbox);
    transpose_kernel<<<dim3(8, 33, 32), dim3(32, 8)>>>(context, indicator);
    conv1_kernel<<<dim3(10, 32), 256>>>(w_in, b_in);
    conv2_kernel<<<dim3(10, 32), 256>>>(w_out, b_out);
    fuse_kernel<<<(B_ * C_ * H_ * (W_ / 4)) / 256, 256>>>(global_x, out);
}